// round 1
// baseline (speedup 1.0000x reference)
#include <cuda_runtime.h>

#define NFEAT 256
#define QBANK 2048
#define DDIM  512
#define CCLS  1000
#define IMGE  150528           // 3*224*224
#define IMG4  (IMGE/4)         // 37632
#define KNN   4

// Scratch (allocation-free rule: __device__ globals)
__device__ float g_binv[QBANK];
__device__ float g_sim[NFEAT * QBANK];
__device__ int   g_idx[NFEAT * KNN];

// ---------------------------------------------------------------------------
// K1: inverse L2 norms of bank rows
// ---------------------------------------------------------------------------
__global__ void k_norm(const float* __restrict__ bank) {
    int j = blockIdx.x;
    const float4* row = reinterpret_cast<const float4*>(bank + (size_t)j * DDIM);
    float s = 0.f;
    for (int t = threadIdx.x; t < DDIM / 4; t += blockDim.x) {
        float4 v = row[t];
        s += v.x * v.x + v.y * v.y + v.z * v.z + v.w * v.w;
    }
    __shared__ float sm[4];
    #pragma unroll
    for (int o = 16; o > 0; o >>= 1) s += __shfl_down_sync(0xffffffffu, s, o);
    if ((threadIdx.x & 31) == 0) sm[threadIdx.x >> 5] = s;
    __syncthreads();
    if (threadIdx.x == 0) {
        float t = sm[0] + sm[1] + sm[2] + sm[3];
        g_binv[j] = 1.0f / sqrtf(fmaxf(t, 1e-24f));
    }
}

// ---------------------------------------------------------------------------
// K2: similarity matrix  sim[i][j] = dot(feat_i, bank_j) * binv[j]
// 64x64 output tile per block, K-chunks of 32, 4x4 per-thread microtile.
// ---------------------------------------------------------------------------
__global__ void k_sim(const float* __restrict__ A, const float* __restrict__ B) {
    __shared__ float As[32][64];
    __shared__ float Bs[32][64];
    int tx = threadIdx.x & 15;
    int ty = threadIdx.x >> 4;
    int i0 = blockIdx.y * 64;
    int j0 = blockIdx.x * 64;
    float acc[4][4] = {};
    for (int k0 = 0; k0 < DDIM; k0 += 32) {
        #pragma unroll
        for (int l = 0; l < 8; l++) {
            int lin = l * 256 + threadIdx.x;
            int r = lin >> 5, k = lin & 31;
            As[k][r] = A[(size_t)(i0 + r) * DDIM + k0 + k];
            Bs[k][r] = B[(size_t)(j0 + r) * DDIM + k0 + k];
        }
        __syncthreads();
        #pragma unroll
        for (int kk = 0; kk < 32; kk++) {
            float4 a = *reinterpret_cast<const float4*>(&As[kk][ty * 4]);
            float4 b = *reinterpret_cast<const float4*>(&Bs[kk][tx * 4]);
            float av[4] = {a.x, a.y, a.z, a.w};
            float bv[4] = {b.x, b.y, b.z, b.w};
            #pragma unroll
            for (int x = 0; x < 4; x++)
                #pragma unroll
                for (int y = 0; y < 4; y++)
                    acc[x][y] += av[x] * bv[y];
        }
        __syncthreads();
    }
    #pragma unroll
    for (int x = 0; x < 4; x++) {
        int i = i0 + ty * 4 + x;
        #pragma unroll
        for (int y = 0; y < 4; y++) {
            int j = j0 + tx * 4 + y;
            g_sim[(size_t)i * QBANK + j] = acc[x][y] * g_binv[j];
        }
    }
}

// ---------------------------------------------------------------------------
// K3: per-row top-4 LARGEST cosine distance == 4 SMALLEST similarity.
// Exact lax.top_k tie semantics: value order, ties -> smaller index, selected
// in descending-distance order (== ascending-similarity selection order).
// ---------------------------------------------------------------------------
__device__ __forceinline__ unsigned sortable_f32(float v) {
    unsigned u = __float_as_uint(v);
    return (u & 0x80000000u) ? ~u : (u | 0x80000000u);
}

__global__ void k_topk() {
    int i = blockIdx.x;
    const float* row = g_sim + (size_t)i * QBANK;
    __shared__ unsigned long long red[256];
    __shared__ int chosen[KNN];
    for (int r = 0; r < KNN; r++) {
        unsigned long long best = ~0ull;
        for (int j = threadIdx.x; j < QBANK; j += 256) {
            bool skip = false;
            for (int p = 0; p < r; p++) if (chosen[p] == j) skip = true;
            if (skip) continue;
            unsigned long long key =
                ((unsigned long long)sortable_f32(row[j]) << 32) | (unsigned)j;
            best = min(best, key);
        }
        red[threadIdx.x] = best;
        __syncthreads();
        for (int s = 128; s > 0; s >>= 1) {
            if (threadIdx.x < s)
                red[threadIdx.x] = min(red[threadIdx.x], red[threadIdx.x + s]);
            __syncthreads();
        }
        if (threadIdx.x == 0) {
            int j = (int)(red[0] & 0xffffffffu);
            chosen[r] = j;
            g_idx[i * KNN + r] = j;
        }
        __syncthreads();
    }
}

// ---------------------------------------------------------------------------
// K4: grads_m = mean of 4 gathered bank_feature rows
// ---------------------------------------------------------------------------
__global__ void k_grads(const float* __restrict__ bank, float* __restrict__ out) {
    int i = blockIdx.x;
    int4 id = *reinterpret_cast<const int4*>(&g_idx[i * 4]);
    const float4* r0 = reinterpret_cast<const float4*>(bank + (size_t)id.x * DDIM);
    const float4* r1 = reinterpret_cast<const float4*>(bank + (size_t)id.y * DDIM);
    const float4* r2 = reinterpret_cast<const float4*>(bank + (size_t)id.z * DDIM);
    const float4* r3 = reinterpret_cast<const float4*>(bank + (size_t)id.w * DDIM);
    float4* o = reinterpret_cast<float4*>(out + (size_t)i * DDIM);
    for (int t = threadIdx.x; t < DDIM / 4; t += blockDim.x) {
        float4 a = r0[t], b = r1[t], c = r2[t], d = r3[t];
        float4 v;
        v.x = (a.x + b.x + c.x + d.x) * 0.25f;
        v.y = (a.y + b.y + c.y + d.y) * 0.25f;
        v.z = (a.z + b.z + c.z + d.z) * 0.25f;
        v.w = (a.w + b.w + c.w + d.w) * 0.25f;
        o[t] = v;
    }
}

// ---------------------------------------------------------------------------
// K5: pred_probs (mean of 4 prob rows) + argmax label (first-index tie-break)
// ---------------------------------------------------------------------------
__global__ void k_probs(const float* __restrict__ probs,
                        float* __restrict__ out_probs,
                        float* __restrict__ out_labels) {
    int i = blockIdx.x;
    int4 id = *reinterpret_cast<const int4*>(&g_idx[i * 4]);
    const float* p0 = probs + (size_t)id.x * CCLS;
    const float* p1 = probs + (size_t)id.y * CCLS;
    const float* p2 = probs + (size_t)id.z * CCLS;
    const float* p3 = probs + (size_t)id.w * CCLS;
    unsigned long long best = 0ull;
    for (int c = threadIdx.x; c < CCLS; c += blockDim.x) {
        float p = (p0[c] + p1[c] + p2[c] + p3[c]) * 0.25f;
        out_probs[(size_t)i * CCLS + c] = p;
        unsigned long long key =
            ((unsigned long long)sortable_f32(p) << 32) | (0xFFFFFFFFu - (unsigned)c);
        best = max(best, key);
    }
    __shared__ unsigned long long red[256];
    red[threadIdx.x] = best;
    __syncthreads();
    for (int s = 128; s > 0; s >>= 1) {
        if (threadIdx.x < s)
            red[threadIdx.x] = max(red[threadIdx.x], red[threadIdx.x + s]);
        __syncthreads();
    }
    if (threadIdx.x == 0) {
        unsigned c = 0xFFFFFFFFu - (unsigned)(red[0] & 0xffffffffu);
        out_labels[i] = (float)c;
    }
}

// ---------------------------------------------------------------------------
// K6: pred_images = mean of 4 gathered images. Grid (i fast, pixel-chunk slow)
// so each execution wave touches ~8 MB of bank per chunk -> L2 reuse of
// repeated indices.
// ---------------------------------------------------------------------------
__global__ void k_img(const float* __restrict__ img, float* __restrict__ out) {
    int i = blockIdx.x;                                    // 0..255 (fast)
    int e4 = blockIdx.y * blockDim.x + threadIdx.x;        // 0..IMG4-1
    int4 id = *reinterpret_cast<const int4*>(&g_idx[i * 4]);
    const float4* im = reinterpret_cast<const float4*>(img);
    float4 a = im[(size_t)id.x * IMG4 + e4];
    float4 b = im[(size_t)id.y * IMG4 + e4];
    float4 c = im[(size_t)id.z * IMG4 + e4];
    float4 d = im[(size_t)id.w * IMG4 + e4];
    float4 v;
    v.x = (a.x + b.x + c.x + d.x) * 0.25f;
    v.y = (a.y + b.y + c.y + d.y) * 0.25f;
    v.z = (a.z + b.z + c.z + d.z) * 0.25f;
    v.w = (a.w + b.w + c.w + d.w) * 0.25f;
    reinterpret_cast<float4*>(out)[(size_t)i * IMG4 + e4] = v;
}

// ---------------------------------------------------------------------------
extern "C" void kernel_launch(void* const* d_in, const int* in_sizes, int n_in,
                              void* d_out, int out_size) {
    const float* features = (const float*)d_in[0];   // (256,512)
    const float* bank     = (const float*)d_in[1];   // (2048,512)
    const float* probs    = (const float*)d_in[2];   // (2048,1000)
    const float* images   = (const float*)d_in[3];   // (2048,3,224,224)
    (void)in_sizes; (void)n_in; (void)out_size;

    float* out        = (float*)d_out;
    float* out_labels = out;                                   // 256
    float* out_probs  = out + NFEAT;                           // 256*1000
    float* out_images = out_probs + (size_t)NFEAT * CCLS;      // 256*150528
    float* out_grads  = out_images + (size_t)NFEAT * IMGE;     // 256*512

    k_norm<<<QBANK, 128>>>(bank);
    k_sim<<<dim3(QBANK / 64, NFEAT / 64), 256>>>(features, bank);
    k_topk<<<NFEAT, 256>>>();
    k_grads<<<NFEAT, 128>>>(bank, out_grads);
    k_probs<<<NFEAT, 256>>>(probs, out_probs, out_labels);
    k_img<<<dim3(NFEAT, IMG4 / 256), 256>>>(images, out_images);
}

// round 2
// speedup vs baseline: 1.0516x; 1.0516x over previous
#include <cuda_runtime.h>

#define NFEAT 256
#define QBANK 2048
#define DDIM  512
#define CCLS  1000
#define IMGE  150528           // 3*224*224
#define IMG4  (IMGE/4)         // 37632
#define KNN   4

// Scratch (allocation-free rule: __device__ globals)
__device__ float g_sim[NFEAT * QBANK];
__device__ int   g_idx[NFEAT * KNN];

__device__ __forceinline__ unsigned sortable_f32(float v) {
    unsigned u = __float_as_uint(v);
    return (u & 0x80000000u) ? ~u : (u | 0x80000000u);
}

// ---------------------------------------------------------------------------
// K1: similarity matrix sim[i][j] = dot(feat_i, bank_j) * binv[j]
// Column norms computed in-block (L2-hot redundant read, removes k_norm).
// 64x64 tile, K-chunks of 32, 4x4 microtile.
// ---------------------------------------------------------------------------
__global__ void k_sim(const float* __restrict__ A, const float* __restrict__ B) {
    __shared__ float As[32][64];
    __shared__ float Bs[32][64];
    __shared__ float binv_s[64];

    int tx = threadIdx.x & 15;
    int ty = threadIdx.x >> 4;
    int i0 = blockIdx.y * 64;
    int j0 = blockIdx.x * 64;

    // ---- fused column norms: 4 threads per j-row ----
    {
        int r = threadIdx.x >> 2;   // 0..63
        int q = threadIdx.x & 3;    // 0..3
        const float4* row = reinterpret_cast<const float4*>(B + (size_t)(j0 + r) * DDIM);
        float s = 0.f;
        for (int t = q; t < DDIM / 4; t += 4) {
            float4 v = row[t];
            s += v.x * v.x + v.y * v.y + v.z * v.z + v.w * v.w;
        }
        s += __shfl_down_sync(0xffffffffu, s, 1);
        s += __shfl_down_sync(0xffffffffu, s, 2);
        if (q == 0) binv_s[r] = 1.0f / sqrtf(fmaxf(s, 1e-24f));
    }

    float acc[4][4] = {};
    for (int k0 = 0; k0 < DDIM; k0 += 32) {
        #pragma unroll
        for (int l = 0; l < 8; l++) {
            int lin = l * 256 + threadIdx.x;
            int r = lin >> 5, k = lin & 31;
            As[k][r] = A[(size_t)(i0 + r) * DDIM + k0 + k];
            Bs[k][r] = B[(size_t)(j0 + r) * DDIM + k0 + k];
        }
        __syncthreads();
        #pragma unroll
        for (int kk = 0; kk < 32; kk++) {
            float4 a = *reinterpret_cast<const float4*>(&As[kk][ty * 4]);
            float4 b = *reinterpret_cast<const float4*>(&Bs[kk][tx * 4]);
            float av[4] = {a.x, a.y, a.z, a.w};
            float bv[4] = {b.x, b.y, b.z, b.w};
            #pragma unroll
            for (int x = 0; x < 4; x++)
                #pragma unroll
                for (int y = 0; y < 4; y++)
                    acc[x][y] += av[x] * bv[y];
        }
        __syncthreads();
    }
    #pragma unroll
    for (int x = 0; x < 4; x++) {
        int i = i0 + ty * 4 + x;
        #pragma unroll
        for (int y = 0; y < 4; y++) {
            int j = j0 + tx * 4 + y;
            g_sim[(size_t)i * QBANK + j] = acc[x][y] * binv_s[tx * 4 + y];
        }
    }
}

// ---------------------------------------------------------------------------
// K2: single-pass top-4 smallest-similarity per row.
// Keys (sortable(sim)<<32)|j are globally comparable -> exact lax.top_k
// semantics (value order, smaller index on tie, ascending-similarity output).
// ---------------------------------------------------------------------------
__device__ __forceinline__ void ins4(unsigned long long v, unsigned long long b[4]) {
    if (v < b[3]) {
        b[3] = v;
        if (b[3] < b[2]) { unsigned long long t = b[2]; b[2] = b[3]; b[3] = t; }
        if (b[2] < b[1]) { unsigned long long t = b[1]; b[1] = b[2]; b[2] = t; }
        if (b[1] < b[0]) { unsigned long long t = b[0]; b[0] = b[1]; b[1] = t; }
    }
}

__global__ void k_topk() {
    int i = blockIdx.x;
    const float* row = g_sim + (size_t)i * QBANK;
    unsigned long long b[4] = {~0ull, ~0ull, ~0ull, ~0ull};
    for (int j = threadIdx.x; j < QBANK; j += 256) {
        unsigned long long key =
            ((unsigned long long)sortable_f32(row[j]) << 32) | (unsigned)j;
        ins4(key, b);
    }
    // warp merge
    #pragma unroll
    for (int o = 16; o > 0; o >>= 1) {
        unsigned long long ov[4];
        #pragma unroll
        for (int t = 0; t < 4; t++) ov[t] = __shfl_down_sync(0xffffffffu, b[t], o);
        #pragma unroll
        for (int t = 0; t < 4; t++) ins4(ov[t], b);
    }
    __shared__ unsigned long long sm[32];
    int wid = threadIdx.x >> 5, lid = threadIdx.x & 31;
    if (lid == 0) {
        #pragma unroll
        for (int t = 0; t < 4; t++) sm[wid * 4 + t] = b[t];
    }
    __syncthreads();
    if (wid == 0) {
        unsigned long long c[4] = {sm[lid], ~0ull, ~0ull, ~0ull};
        #pragma unroll
        for (int o = 16; o > 0; o >>= 1) {
            unsigned long long ov[4];
            #pragma unroll
            for (int t = 0; t < 4; t++) ov[t] = __shfl_down_sync(0xffffffffu, c[t], o);
            #pragma unroll
            for (int t = 0; t < 4; t++) ins4(ov[t], c);
        }
        if (lid == 0) {
            #pragma unroll
            for (int t = 0; t < 4; t++) g_idx[i * KNN + t] = (int)(c[t] & 0xffffffffu);
        }
    }
}

// ---------------------------------------------------------------------------
// K3: fused gather epilogue.
//   y < 147 : image mean chunk (i fast in x -> L2 reuse of gathered images;
//             streaming stores keep output from evicting the gather set)
//   y == 147: grads_m + pred_probs + argmax label for row i
// ---------------------------------------------------------------------------
__global__ void k_gather(const float* __restrict__ img,
                         const float* __restrict__ bank,
                         const float* __restrict__ probs,
                         float* __restrict__ out_images,
                         float* __restrict__ out_grads,
                         float* __restrict__ out_probs,
                         float* __restrict__ out_labels) {
    int i = blockIdx.x;
    int4 id = *reinterpret_cast<const int4*>(&g_idx[i * 4]);

    if (blockIdx.y < IMG4 / 256) {
        int e4 = blockIdx.y * blockDim.x + threadIdx.x;
        const float4* im = reinterpret_cast<const float4*>(img);
        float4 a = im[(size_t)id.x * IMG4 + e4];
        float4 b = im[(size_t)id.y * IMG4 + e4];
        float4 c = im[(size_t)id.z * IMG4 + e4];
        float4 d = im[(size_t)id.w * IMG4 + e4];
        float4 v;
        v.x = (a.x + b.x + c.x + d.x) * 0.25f;
        v.y = (a.y + b.y + c.y + d.y) * 0.25f;
        v.z = (a.z + b.z + c.z + d.z) * 0.25f;
        v.w = (a.w + b.w + c.w + d.w) * 0.25f;
        __stcs(reinterpret_cast<float4*>(out_images) + (size_t)i * IMG4 + e4, v);
        return;
    }

    // ---- grads_m: 128 float4 ----
    if (threadIdx.x < DDIM / 4) {
        int t = threadIdx.x;
        const float4* r0 = reinterpret_cast<const float4*>(bank + (size_t)id.x * DDIM);
        const float4* r1 = reinterpret_cast<const float4*>(bank + (size_t)id.y * DDIM);
        const float4* r2 = reinterpret_cast<const float4*>(bank + (size_t)id.z * DDIM);
        const float4* r3 = reinterpret_cast<const float4*>(bank + (size_t)id.w * DDIM);
        float4 a = r0[t], b = r1[t], c = r2[t], d = r3[t];
        float4 v;
        v.x = (a.x + b.x + c.x + d.x) * 0.25f;
        v.y = (a.y + b.y + c.y + d.y) * 0.25f;
        v.z = (a.z + b.z + c.z + d.z) * 0.25f;
        v.w = (a.w + b.w + c.w + d.w) * 0.25f;
        reinterpret_cast<float4*>(out_grads + (size_t)i * DDIM)[t] = v;
    }

    // ---- pred_probs + argmax ----
    const float* p0 = probs + (size_t)id.x * CCLS;
    const float* p1 = probs + (size_t)id.y * CCLS;
    const float* p2 = probs + (size_t)id.z * CCLS;
    const float* p3 = probs + (size_t)id.w * CCLS;
    unsigned long long best = 0ull;
    for (int c = threadIdx.x; c < CCLS; c += blockDim.x) {
        float p = (p0[c] + p1[c] + p2[c] + p3[c]) * 0.25f;
        out_probs[(size_t)i * CCLS + c] = p;
        unsigned long long key =
            ((unsigned long long)sortable_f32(p) << 32) | (0xFFFFFFFFu - (unsigned)c);
        best = max(best, key);
    }
    #pragma unroll
    for (int o = 16; o > 0; o >>= 1)
        best = max(best, __shfl_down_sync(0xffffffffu, best, o));
    __shared__ unsigned long long red[8];
    int wid = threadIdx.x >> 5, lid = threadIdx.x & 31;
    if (lid == 0) red[wid] = best;
    __syncthreads();
    if (threadIdx.x == 0) {
        unsigned long long m = red[0];
        #pragma unroll
        for (int w = 1; w < 8; w++) m = max(m, red[w]);
        unsigned c = 0xFFFFFFFFu - (unsigned)(m & 0xffffffffu);
        out_labels[i] = (float)c;
    }
}

// ---------------------------------------------------------------------------
extern "C" void kernel_launch(void* const* d_in, const int* in_sizes, int n_in,
                              void* d_out, int out_size) {
    const float* features = (const float*)d_in[0];   // (256,512)
    const float* bank     = (const float*)d_in[1];   // (2048,512)
    const float* probs    = (const float*)d_in[2];   // (2048,1000)
    const float* images   = (const float*)d_in[3];   // (2048,3,224,224)
    (void)in_sizes; (void)n_in; (void)out_size;

    float* out        = (float*)d_out;
    float* out_labels = out;                                   // 256
    float* out_probs  = out + NFEAT;                           // 256*1000
    float* out_images = out_probs + (size_t)NFEAT * CCLS;      // 256*150528
    float* out_grads  = out_images + (size_t)NFEAT * IMGE;     // 256*512

    k_sim<<<dim3(QBANK / 64, NFEAT / 64), 256>>>(features, bank);
    k_topk<<<NFEAT, 256>>>();
    k_gather<<<dim3(NFEAT, IMG4 / 256 + 1), 256>>>(
        images, bank, probs, out_images, out_grads, out_probs, out_labels);
}

// round 3
// speedup vs baseline: 1.1845x; 1.1263x over previous
#include <cuda_runtime.h>

#define NFEAT 256
#define QBANK 2048
#define DDIM  512
#define CCLS  1000
#define IMGE  150528           // 3*224*224
#define IMG4  (IMGE/4)         // 37632
#define KNN   4

// Scratch (allocation-free rule: __device__ globals)
__device__ float g_binv[QBANK];
__device__ float g_AT2[DDIM * NFEAT * 2];   // [k][i] duplicated pairs (float2)
__device__ float g_BT[DDIM * QBANK];        // [k][j]
__device__ float g_sim[NFEAT * QBANK];
__device__ int   g_idx[NFEAT * KNN];

__device__ __forceinline__ unsigned sortable_f32(float v) {
    unsigned u = __float_as_uint(v);
    return (u & 0x80000000u) ? ~u : (u | 0x80000000u);
}

__device__ __forceinline__ void ffma2(unsigned long long& acc,
                                      unsigned long long a,
                                      unsigned long long b) {
    asm("fma.rn.f32x2 %0, %1, %2, %0;" : "+l"(acc) : "l"(a), "l"(b));
}
__device__ __forceinline__ unsigned long long pk2(float lo, float hi) {
    unsigned long long r;
    asm("mov.b64 %0, {%1, %2};" : "=l"(r) : "f"(lo), "f"(hi));
    return r;
}
__device__ __forceinline__ float2 unpk2(unsigned long long v) {
    float lo, hi;
    asm("mov.b64 {%0, %1}, %2;" : "=f"(lo), "=f"(hi) : "l"(v));
    return make_float2(lo, hi);
}

// ---------------------------------------------------------------------------
// K0: inverse L2 norms of bank rows
// ---------------------------------------------------------------------------
__global__ void k_norm(const float* __restrict__ bank) {
    int j = blockIdx.x;
    const float4* row = reinterpret_cast<const float4*>(bank + (size_t)j * DDIM);
    float s = 0.f;
    for (int t = threadIdx.x; t < DDIM / 4; t += blockDim.x) {
        float4 v = row[t];
        s += v.x * v.x + v.y * v.y + v.z * v.z + v.w * v.w;
    }
    __shared__ float sm[4];
    #pragma unroll
    for (int o = 16; o > 0; o >>= 1) s += __shfl_down_sync(0xffffffffu, s, o);
    if ((threadIdx.x & 31) == 0) sm[threadIdx.x >> 5] = s;
    __syncthreads();
    if (threadIdx.x == 0) {
        float t = sm[0] + sm[1] + sm[2] + sm[3];
        g_binv[j] = 1.0f / sqrtf(fmaxf(t, 1e-24f));
    }
}

// ---------------------------------------------------------------------------
// K1: transpose A -> AT2 (k-major, duplicated pairs) and B -> BT (k-major).
// 32x32 tiles, 256 threads. Blocks: 128 A-tiles then 1024 B-tiles.
// ---------------------------------------------------------------------------
__global__ void k_prep(const float* __restrict__ A, const float* __restrict__ B) {
    __shared__ float t[32][33];
    int id = blockIdx.x;
    int tx = threadIdx.x & 31;
    int ty = threadIdx.x >> 5;          // 0..7
    if (id < 128) {                     // A: (256 i, 512 k) tiles: it 0..7, kt 0..15
        int it = id >> 4, kt = id & 15;
        int i0 = it * 32, k0 = kt * 32;
        #pragma unroll
        for (int rr = 0; rr < 4; rr++) {
            int r = ty + rr * 8;
            t[r][tx] = A[(size_t)(i0 + r) * DDIM + k0 + tx];
        }
        __syncthreads();
        #pragma unroll
        for (int rr = 0; rr < 4; rr++) {
            int r = ty + rr * 8;        // k within tile
            float v = t[tx][r];
            reinterpret_cast<float2*>(g_AT2)[(size_t)(k0 + r) * NFEAT + i0 + tx] =
                make_float2(v, v);
        }
    } else {                            // B: (2048 j, 512 k) tiles: jt 0..63, kt 0..15
        int id2 = id - 128;
        int jt = id2 >> 4, kt = id2 & 15;
        int j0 = jt * 32, k0 = kt * 32;
        #pragma unroll
        for (int rr = 0; rr < 4; rr++) {
            int r = ty + rr * 8;
            t[r][tx] = B[(size_t)(j0 + r) * DDIM + k0 + tx];
        }
        __syncthreads();
        #pragma unroll
        for (int rr = 0; rr < 4; rr++) {
            int r = ty + rr * 8;
            g_BT[(size_t)(k0 + r) * QBANK + j0 + tx] = t[tx][r];
        }
    }
}

// ---------------------------------------------------------------------------
// K2: sim[i][j] = dot(feat_i, bank_j)  (raw; binv applied in topk)
// 32i x 64j tile per block, BK=32, 128 threads, 4i x 4j microtile, FFMA2.
// grid (32 j-tiles, 8 i-tiles) = 256 blocks.
// ---------------------------------------------------------------------------
__global__ void __launch_bounds__(128) k_sim() {
    __shared__ float2 As2[32][32];      // [k][i] dup pairs, 8KB
    __shared__ float  Bs[32][64];       // [k][j], 8KB

    int tid = threadIdx.x;
    int tx = tid & 15;                  // j/4
    int ty = tid >> 4;                  // i/4 (0..7)
    int i0 = blockIdx.y * 32;
    int j0 = blockIdx.x * 64;

    unsigned long long acc[4][2];
    #pragma unroll
    for (int x = 0; x < 4; x++)
        #pragma unroll
        for (int y = 0; y < 2; y++) acc[x][y] = pk2(0.f, 0.f);

    #pragma unroll 1
    for (int k0 = 0; k0 < DDIM; k0 += 32) {
        // load As2: 32 rows x 32 float2 = 512 float4 -> 4 per thread
        #pragma unroll
        for (int q = 0; q < 4; q++) {
            int lin = q * 128 + tid;
            int r = lin >> 4, c4 = lin & 15;
            reinterpret_cast<float4*>(&As2[r][0])[c4] =
                reinterpret_cast<const float4*>(g_AT2 + ((size_t)(k0 + r) * NFEAT + i0) * 2)[c4];
        }
        // load Bs: 32 rows x 64 floats = 512 float4 -> 4 per thread
        #pragma unroll
        for (int q = 0; q < 4; q++) {
            int lin = q * 128 + tid;
            int r = lin >> 4, c4 = lin & 15;
            reinterpret_cast<float4*>(&Bs[r][0])[c4] =
                reinterpret_cast<const float4*>(g_BT + (size_t)(k0 + r) * QBANK + j0)[c4];
        }
        __syncthreads();
        #pragma unroll
        for (int kk = 0; kk < 32; kk++) {
            float4 a01 = *reinterpret_cast<const float4*>(&As2[kk][ty * 4]);
            float4 a23 = *reinterpret_cast<const float4*>(&As2[kk][ty * 4 + 2]);
            float4 bv  = *reinterpret_cast<const float4*>(&Bs[kk][tx * 4]);
            unsigned long long b01 = pk2(bv.x, bv.y);
            unsigned long long b23 = pk2(bv.z, bv.w);
            unsigned long long a0 = pk2(a01.x, a01.y);
            unsigned long long a1 = pk2(a01.z, a01.w);
            unsigned long long a2 = pk2(a23.x, a23.y);
            unsigned long long a3 = pk2(a23.z, a23.w);
            ffma2(acc[0][0], a0, b01); ffma2(acc[0][1], a0, b23);
            ffma2(acc[1][0], a1, b01); ffma2(acc[1][1], a1, b23);
            ffma2(acc[2][0], a2, b01); ffma2(acc[2][1], a2, b23);
            ffma2(acc[3][0], a3, b01); ffma2(acc[3][1], a3, b23);
        }
        __syncthreads();
    }
    #pragma unroll
    for (int x = 0; x < 4; x++) {
        int i = i0 + ty * 4 + x;
        #pragma unroll
        for (int y = 0; y < 2; y++) {
            float2 v = unpk2(acc[x][y]);
            *reinterpret_cast<float2*>(&g_sim[(size_t)i * QBANK + j0 + tx * 4 + y * 2]) = v;
        }
    }
}

// ---------------------------------------------------------------------------
// K3: single-pass top-4 smallest similarity per row (binv applied here).
// Keys (sortable(sim*binv)<<32)|j -> exact lax.top_k tie semantics.
// ---------------------------------------------------------------------------
__device__ __forceinline__ void ins4(unsigned long long v, unsigned long long b[4]) {
    if (v < b[3]) {
        b[3] = v;
        if (b[3] < b[2]) { unsigned long long t = b[2]; b[2] = b[3]; b[3] = t; }
        if (b[2] < b[1]) { unsigned long long t = b[1]; b[1] = b[2]; b[2] = t; }
        if (b[1] < b[0]) { unsigned long long t = b[0]; b[0] = b[1]; b[1] = t; }
    }
}

__global__ void k_topk() {
    int i = blockIdx.x;
    const float* row = g_sim + (size_t)i * QBANK;
    unsigned long long b[4] = {~0ull, ~0ull, ~0ull, ~0ull};
    for (int j = threadIdx.x; j < QBANK; j += 256) {
        float s = row[j] * g_binv[j];
        unsigned long long key =
            ((unsigned long long)sortable_f32(s) << 32) | (unsigned)j;
        ins4(key, b);
    }
    #pragma unroll
    for (int o = 16; o > 0; o >>= 1) {
        unsigned long long ov[4];
        #pragma unroll
        for (int t = 0; t < 4; t++) ov[t] = __shfl_down_sync(0xffffffffu, b[t], o);
        #pragma unroll
        for (int t = 0; t < 4; t++) ins4(ov[t], b);
    }
    __shared__ unsigned long long sm[32];
    int wid = threadIdx.x >> 5, lid = threadIdx.x & 31;
    if (lid == 0) {
        #pragma unroll
        for (int t = 0; t < 4; t++) sm[wid * 4 + t] = b[t];
    }
    __syncthreads();
    if (wid == 0) {
        unsigned long long c[4] = {sm[lid], ~0ull, ~0ull, ~0ull};
        #pragma unroll
        for (int o = 16; o > 0; o >>= 1) {
            unsigned long long ov[4];
            #pragma unroll
            for (int t = 0; t < 4; t++) ov[t] = __shfl_down_sync(0xffffffffu, c[t], o);
            #pragma unroll
            for (int t = 0; t < 4; t++) ins4(ov[t], c);
        }
        if (lid == 0) {
            #pragma unroll
            for (int t = 0; t < 4; t++) g_idx[i * KNN + t] = (int)(c[t] & 0xffffffffu);
        }
    }
}

// ---------------------------------------------------------------------------
// K4: fused gather epilogue (images + grads + probs + labels)
// ---------------------------------------------------------------------------
__global__ void k_gather(const float* __restrict__ img,
                         const float* __restrict__ bank,
                         const float* __restrict__ probs,
                         float* __restrict__ out_images,
                         float* __restrict__ out_grads,
                         float* __restrict__ out_probs,
                         float* __restrict__ out_labels) {
    int i = blockIdx.x;
    int4 id = *reinterpret_cast<const int4*>(&g_idx[i * 4]);

    if (blockIdx.y < IMG4 / 256) {
        int e4 = blockIdx.y * blockDim.x + threadIdx.x;
        const float4* im = reinterpret_cast<const float4*>(img);
        float4 a = im[(size_t)id.x * IMG4 + e4];
        float4 b = im[(size_t)id.y * IMG4 + e4];
        float4 c = im[(size_t)id.z * IMG4 + e4];
        float4 d = im[(size_t)id.w * IMG4 + e4];
        float4 v;
        v.x = (a.x + b.x + c.x + d.x) * 0.25f;
        v.y = (a.y + b.y + c.y + d.y) * 0.25f;
        v.z = (a.z + b.z + c.z + d.z) * 0.25f;
        v.w = (a.w + b.w + c.w + d.w) * 0.25f;
        __stcs(reinterpret_cast<float4*>(out_images) + (size_t)i * IMG4 + e4, v);
        return;
    }

    // grads_m
    if (threadIdx.x < DDIM / 4) {
        int t = threadIdx.x;
        const float4* r0 = reinterpret_cast<const float4*>(bank + (size_t)id.x * DDIM);
        const float4* r1 = reinterpret_cast<const float4*>(bank + (size_t)id.y * DDIM);
        const float4* r2 = reinterpret_cast<const float4*>(bank + (size_t)id.z * DDIM);
        const float4* r3 = reinterpret_cast<const float4*>(bank + (size_t)id.w * DDIM);
        float4 a = r0[t], b = r1[t], c = r2[t], d = r3[t];
        float4 v;
        v.x = (a.x + b.x + c.x + d.x) * 0.25f;
        v.y = (a.y + b.y + c.y + d.y) * 0.25f;
        v.z = (a.z + b.z + c.z + d.z) * 0.25f;
        v.w = (a.w + b.w + c.w + d.w) * 0.25f;
        reinterpret_cast<float4*>(out_grads + (size_t)i * DDIM)[t] = v;
    }

    // pred_probs + argmax
    const float* p0 = probs + (size_t)id.x * CCLS;
    const float* p1 = probs + (size_t)id.y * CCLS;
    const float* p2 = probs + (size_t)id.z * CCLS;
    const float* p3 = probs + (size_t)id.w * CCLS;
    unsigned long long best = 0ull;
    for (int c = threadIdx.x; c < CCLS; c += blockDim.x) {
        float p = (p0[c] + p1[c] + p2[c] + p3[c]) * 0.25f;
        out_probs[(size_t)i * CCLS + c] = p;
        unsigned long long key =
            ((unsigned long long)sortable_f32(p) << 32) | (0xFFFFFFFFu - (unsigned)c);
        best = max(best, key);
    }
    #pragma unroll
    for (int o = 16; o > 0; o >>= 1)
        best = max(best, __shfl_down_sync(0xffffffffu, best, o));
    __shared__ unsigned long long red[8];
    int wid = threadIdx.x >> 5, lid = threadIdx.x & 31;
    if (lid == 0) red[wid] = best;
    __syncthreads();
    if (threadIdx.x == 0) {
        unsigned long long m = red[0];
        #pragma unroll
        for (int w = 1; w < 8; w++) m = max(m, red[w]);
        unsigned c = 0xFFFFFFFFu - (unsigned)(m & 0xffffffffu);
        out_labels[i] = (float)c;
    }
}

// ---------------------------------------------------------------------------
extern "C" void kernel_launch(void* const* d_in, const int* in_sizes, int n_in,
                              void* d_out, int out_size) {
    const float* features = (const float*)d_in[0];   // (256,512)
    const float* bank     = (const float*)d_in[1];   // (2048,512)
    const float* probs    = (const float*)d_in[2];   // (2048,1000)
    const float* images   = (const float*)d_in[3];   // (2048,3,224,224)
    (void)in_sizes; (void)n_in; (void)out_size;

    float* out        = (float*)d_out;
    float* out_labels = out;                                   // 256
    float* out_probs  = out + NFEAT;                           // 256*1000
    float* out_images = out_probs + (size_t)NFEAT * CCLS;      // 256*150528
    float* out_grads  = out_images + (size_t)NFEAT * IMGE;     // 256*512

    k_norm<<<QBANK, 128>>>(bank);
    k_prep<<<128 + 1024, 256>>>(features, bank);
    k_sim<<<dim3(QBANK / 64, NFEAT / 32), 128>>>();
    k_topk<<<NFEAT, 256>>>();
    k_gather<<<dim3(NFEAT, IMG4 / 256 + 1), 256>>>(
        images, bank, probs, out_images, out_grads, out_probs, out_labels);
}

// round 4
// speedup vs baseline: 1.2745x; 1.0760x over previous
#include <cuda_runtime.h>

#define NFEAT 256
#define QBANK 2048
#define DDIM  512
#define CCLS  1000
#define IMGE  150528           // 3*224*224
#define IMG4  (IMGE/4)         // 37632
#define KNN   4
#define NJBLK (QBANK / 64)     // 32

// Scratch (allocation-free rule: __device__ globals)
__device__ float g_binv[QBANK];
__device__ float g_AT2[DDIM * NFEAT * 2];               // [k][i] dup pairs
__device__ float g_BT[DDIM * QBANK];                    // [k][j]
__device__ unsigned long long g_cand[NFEAT * NJBLK * 4]; // per-row per-jblk top4 keys
__device__ int   g_idx[NFEAT * KNN];

__device__ __forceinline__ unsigned sortable_f32(float v) {
    unsigned u = __float_as_uint(v);
    return (u & 0x80000000u) ? ~u : (u | 0x80000000u);
}
__device__ __forceinline__ void ffma2(unsigned long long& acc,
                                      unsigned long long a,
                                      unsigned long long b) {
    asm("fma.rn.f32x2 %0, %1, %2, %0;" : "+l"(acc) : "l"(a), "l"(b));
}
__device__ __forceinline__ unsigned long long pk2(float lo, float hi) {
    unsigned long long r;
    asm("mov.b64 %0, {%1, %2};" : "=l"(r) : "f"(lo), "f"(hi));
    return r;
}
__device__ __forceinline__ float2 unpk2(unsigned long long v) {
    float lo, hi;
    asm("mov.b64 {%0, %1}, %2;" : "=f"(lo), "=f"(hi) : "l"(v));
    return make_float2(lo, hi);
}
__device__ __forceinline__ void ins4(unsigned long long v, unsigned long long b[4]) {
    if (v < b[3]) {
        b[3] = v;
        if (b[3] < b[2]) { unsigned long long t = b[2]; b[2] = b[3]; b[3] = t; }
        if (b[2] < b[1]) { unsigned long long t = b[1]; b[1] = b[2]; b[2] = t; }
        if (b[1] < b[0]) { unsigned long long t = b[0]; b[0] = b[1]; b[1] = t; }
    }
}

// ---------------------------------------------------------------------------
// K1: prep — blocks [0,128): A->AT2 transpose (dup pairs)
//            blocks [128,1152): B->BT transpose
//            blocks [1152,1408): bank row inverse norms (8 rows/block)
// ---------------------------------------------------------------------------
__global__ void k_prep(const float* __restrict__ A, const float* __restrict__ B) {
    int id = blockIdx.x;
    if (id >= 1152) {                   // norms: warp per row
        int wid = threadIdx.x >> 5, lid = threadIdx.x & 31;
        int j = (id - 1152) * 8 + wid;
        const float4* row = reinterpret_cast<const float4*>(B + (size_t)j * DDIM);
        float s = 0.f;
        #pragma unroll
        for (int t = 0; t < 4; t++) {
            float4 v = row[lid + t * 32];
            s += v.x * v.x + v.y * v.y + v.z * v.z + v.w * v.w;
        }
        #pragma unroll
        for (int o = 16; o > 0; o >>= 1) s += __shfl_down_sync(0xffffffffu, s, o);
        if (lid == 0) g_binv[j] = 1.0f / sqrtf(fmaxf(s, 1e-24f));
        return;
    }
    __shared__ float t[32][33];
    int tx = threadIdx.x & 31;
    int ty = threadIdx.x >> 5;          // 0..7
    if (id < 128) {                     // A: it 0..7, kt 0..15
        int it = id >> 4, kt = id & 15;
        int i0 = it * 32, k0 = kt * 32;
        #pragma unroll
        for (int rr = 0; rr < 4; rr++) {
            int r = ty + rr * 8;
            t[r][tx] = A[(size_t)(i0 + r) * DDIM + k0 + tx];
        }
        __syncthreads();
        #pragma unroll
        for (int rr = 0; rr < 4; rr++) {
            int r = ty + rr * 8;
            float v = t[tx][r];
            reinterpret_cast<float2*>(g_AT2)[(size_t)(k0 + r) * NFEAT + i0 + tx] =
                make_float2(v, v);
        }
    } else {                            // B: jt 0..63, kt 0..15
        int id2 = id - 128;
        int jt = id2 >> 4, kt = id2 & 15;
        int j0 = jt * 32, k0 = kt * 32;
        #pragma unroll
        for (int rr = 0; rr < 4; rr++) {
            int r = ty + rr * 8;
            t[r][tx] = B[(size_t)(j0 + r) * DDIM + k0 + tx];
        }
        __syncthreads();
        #pragma unroll
        for (int rr = 0; rr < 4; rr++) {
            int r = ty + rr * 8;
            g_BT[(size_t)(k0 + r) * QBANK + j0 + tx] = t[tx][r];
        }
    }
}

// ---------------------------------------------------------------------------
// K2: GEMM (FFMA2) + fused local top-4 epilogue.
// 32i x 64j tile, 128 threads, 4i x 4j microtile.
// Epilogue: per row, merge 16 lanes' 4-candidate lists -> g_cand[i][jblk][4].
// ---------------------------------------------------------------------------
__global__ void __launch_bounds__(128) k_sim() {
    __shared__ float2 As2[32][32];
    __shared__ float  Bs[32][64];
    __shared__ float  binv_s[64];

    int tid = threadIdx.x;
    int tx = tid & 15;
    int ty = tid >> 4;
    int i0 = blockIdx.y * 32;
    int j0 = blockIdx.x * 64;

    if (tid < 64) binv_s[tid] = g_binv[j0 + tid];

    unsigned long long acc[4][2];
    #pragma unroll
    for (int x = 0; x < 4; x++)
        #pragma unroll
        for (int y = 0; y < 2; y++) acc[x][y] = pk2(0.f, 0.f);

    #pragma unroll 1
    for (int k0 = 0; k0 < DDIM; k0 += 32) {
        #pragma unroll
        for (int q = 0; q < 4; q++) {
            int lin = q * 128 + tid;
            int r = lin >> 4, c4 = lin & 15;
            reinterpret_cast<float4*>(&As2[r][0])[c4] =
                reinterpret_cast<const float4*>(g_AT2 + ((size_t)(k0 + r) * NFEAT + i0) * 2)[c4];
        }
        #pragma unroll
        for (int q = 0; q < 4; q++) {
            int lin = q * 128 + tid;
            int r = lin >> 4, c4 = lin & 15;
            reinterpret_cast<float4*>(&Bs[r][0])[c4] =
                reinterpret_cast<const float4*>(g_BT + (size_t)(k0 + r) * QBANK + j0)[c4];
        }
        __syncthreads();
        #pragma unroll
        for (int kk = 0; kk < 32; kk++) {
            float4 a01 = *reinterpret_cast<const float4*>(&As2[kk][ty * 4]);
            float4 a23 = *reinterpret_cast<const float4*>(&As2[kk][ty * 4 + 2]);
            float4 bv  = *reinterpret_cast<const float4*>(&Bs[kk][tx * 4]);
            unsigned long long b01 = pk2(bv.x, bv.y);
            unsigned long long b23 = pk2(bv.z, bv.w);
            unsigned long long a0 = pk2(a01.x, a01.y);
            unsigned long long a1 = pk2(a01.z, a01.w);
            unsigned long long a2 = pk2(a23.x, a23.y);
            unsigned long long a3 = pk2(a23.z, a23.w);
            ffma2(acc[0][0], a0, b01); ffma2(acc[0][1], a0, b23);
            ffma2(acc[1][0], a1, b01); ffma2(acc[1][1], a1, b23);
            ffma2(acc[2][0], a2, b01); ffma2(acc[2][1], a2, b23);
            ffma2(acc[3][0], a3, b01); ffma2(acc[3][1], a3, b23);
        }
        __syncthreads();
    }

    // ---- fused local top-4 per row ----
    float bv0 = binv_s[tx * 4 + 0];
    float bv1 = binv_s[tx * 4 + 1];
    float bv2 = binv_s[tx * 4 + 2];
    float bv3 = binv_s[tx * 4 + 3];
    unsigned jbase = (unsigned)(j0 + tx * 4);
    #pragma unroll
    for (int x = 0; x < 4; x++) {
        float2 v01 = unpk2(acc[x][0]);
        float2 v23 = unpk2(acc[x][1]);
        unsigned long long b[4] = {~0ull, ~0ull, ~0ull, ~0ull};
        ins4(((unsigned long long)sortable_f32(v01.x * bv0) << 32) | (jbase + 0), b);
        ins4(((unsigned long long)sortable_f32(v01.y * bv1) << 32) | (jbase + 1), b);
        ins4(((unsigned long long)sortable_f32(v23.x * bv2) << 32) | (jbase + 2), b);
        ins4(((unsigned long long)sortable_f32(v23.y * bv3) << 32) | (jbase + 3), b);
        #pragma unroll
        for (int o = 8; o > 0; o >>= 1) {
            unsigned long long ov[4];
            #pragma unroll
            for (int t = 0; t < 4; t++) ov[t] = __shfl_down_sync(0xffffffffu, b[t], o);
            #pragma unroll
            for (int t = 0; t < 4; t++) ins4(ov[t], b);
        }
        if (tx == 0) {
            int i = i0 + ty * 4 + x;
            unsigned long long* dst = &g_cand[((size_t)i * NJBLK + blockIdx.x) * 4];
            #pragma unroll
            for (int t = 0; t < 4; t++) dst[t] = b[t];
        }
    }
}

// ---------------------------------------------------------------------------
// K3: final top-4 merge — one warp per row, 128 candidates per row.
// ---------------------------------------------------------------------------
__global__ void k_topk2() {
    int wid = threadIdx.x >> 5, lid = threadIdx.x & 31;
    int i = blockIdx.x * 8 + wid;
    const unsigned long long* cand = &g_cand[(size_t)i * NJBLK * 4];
    unsigned long long b[4] = {~0ull, ~0ull, ~0ull, ~0ull};
    #pragma unroll
    for (int t = 0; t < 4; t++) ins4(cand[lid + t * 32], b);
    #pragma unroll
    for (int o = 16; o > 0; o >>= 1) {
        unsigned long long ov[4];
        #pragma unroll
        for (int t = 0; t < 4; t++) ov[t] = __shfl_down_sync(0xffffffffu, b[t], o);
        #pragma unroll
        for (int t = 0; t < 4; t++) ins4(ov[t], b);
    }
    if (lid == 0) {
        #pragma unroll
        for (int t = 0; t < 4; t++) g_idx[i * KNN + t] = (int)(b[t] & 0xffffffffu);
    }
}

// ---------------------------------------------------------------------------
// K4: fused gather epilogue (images + grads + probs + labels).
// Image blocks: 3 float4 chunks per thread (higher MLP).
// ---------------------------------------------------------------------------
__global__ void k_gather(const float* __restrict__ img,
                         const float* __restrict__ bank,
                         const float* __restrict__ probs,
                         float* __restrict__ out_images,
                         float* __restrict__ out_grads,
                         float* __restrict__ out_probs,
                         float* __restrict__ out_labels) {
    int i = blockIdx.x;
    int4 id = *reinterpret_cast<const int4*>(&g_idx[i * 4]);

    if (blockIdx.y < 49) {
        int base = blockIdx.y * 768 + threadIdx.x;
        const float4* im = reinterpret_cast<const float4*>(img);
        size_t r0 = (size_t)id.x * IMG4, r1 = (size_t)id.y * IMG4;
        size_t r2 = (size_t)id.z * IMG4, r3 = (size_t)id.w * IMG4;
        float4* o = reinterpret_cast<float4*>(out_images) + (size_t)i * IMG4;
        #pragma unroll
        for (int q = 0; q < 3; q++) {
            int e4 = base + q * 256;
            float4 a = im[r0 + e4];
            float4 b = im[r1 + e4];
            float4 c = im[r2 + e4];
            float4 d = im[r3 + e4];
            float4 v;
            v.x = (a.x + b.x + c.x + d.x) * 0.25f;
            v.y = (a.y + b.y + c.y + d.y) * 0.25f;
            v.z = (a.z + b.z + c.z + d.z) * 0.25f;
            v.w = (a.w + b.w + c.w + d.w) * 0.25f;
            __stcs(o + e4, v);
        }
        return;
    }

    // grads_m
    if (threadIdx.x < DDIM / 4) {
        int t = threadIdx.x;
        const float4* r0 = reinterpret_cast<const float4*>(bank + (size_t)id.x * DDIM);
        const float4* r1 = reinterpret_cast<const float4*>(bank + (size_t)id.y * DDIM);
        const float4* r2 = reinterpret_cast<const float4*>(bank + (size_t)id.z * DDIM);
        const float4* r3 = reinterpret_cast<const float4*>(bank + (size_t)id.w * DDIM);
        float4 a = r0[t], b = r1[t], c = r2[t], d = r3[t];
        float4 v;
        v.x = (a.x + b.x + c.x + d.x) * 0.25f;
        v.y = (a.y + b.y + c.y + d.y) * 0.25f;
        v.z = (a.z + b.z + c.z + d.z) * 0.25f;
        v.w = (a.w + b.w + c.w + d.w) * 0.25f;
        reinterpret_cast<float4*>(out_grads + (size_t)i * DDIM)[t] = v;
    }

    // pred_probs + argmax
    const float* p0 = probs + (size_t)id.x * CCLS;
    const float* p1 = probs + (size_t)id.y * CCLS;
    const float* p2 = probs + (size_t)id.z * CCLS;
    const float* p3 = probs + (size_t)id.w * CCLS;
    unsigned long long best = 0ull;
    for (int c = threadIdx.x; c < CCLS; c += blockDim.x) {
        float p = (p0[c] + p1[c] + p2[c] + p3[c]) * 0.25f;
        out_probs[(size_t)i * CCLS + c] = p;
        unsigned long long key =
            ((unsigned long long)sortable_f32(p) << 32) | (0xFFFFFFFFu - (unsigned)c);
        best = max(best, key);
    }
    #pragma unroll
    for (int o = 16; o > 0; o >>= 1)
        best = max(best, __shfl_down_sync(0xffffffffu, best, o));
    __shared__ unsigned long long red[8];
    int wid = threadIdx.x >> 5, lid = threadIdx.x & 31;
    if (lid == 0) red[wid] = best;
    __syncthreads();
    if (threadIdx.x == 0) {
        unsigned long long m = red[0];
        #pragma unroll
        for (int w = 1; w < 8; w++) m = max(m, red[w]);
        unsigned c = 0xFFFFFFFFu - (unsigned)(m & 0xffffffffu);
        out_labels[i] = (float)c;
    }
}

// ---------------------------------------------------------------------------
extern "C" void kernel_launch(void* const* d_in, const int* in_sizes, int n_in,
                              void* d_out, int out_size) {
    const float* features = (const float*)d_in[0];   // (256,512)
    const float* bank     = (const float*)d_in[1];   // (2048,512)
    const float* probs    = (const float*)d_in[2];   // (2048,1000)
    const float* images   = (const float*)d_in[3];   // (2048,3,224,224)
    (void)in_sizes; (void)n_in; (void)out_size;

    float* out        = (float*)d_out;
    float* out_labels = out;                                   // 256
    float* out_probs  = out + NFEAT;                           // 256*1000
    float* out_images = out_probs + (size_t)NFEAT * CCLS;      // 256*150528
    float* out_grads  = out_images + (size_t)NFEAT * IMGE;     // 256*512

    k_prep<<<1152 + 256, 256>>>(features, bank);
    k_sim<<<dim3(NJBLK, NFEAT / 32), 128>>>();
    k_topk2<<<NFEAT / 8, 256>>>();
    k_gather<<<dim3(NFEAT, 49 + 1), 256>>>(
        images, bank, probs, out_images, out_grads, out_probs, out_labels);
}